// round 5
// baseline (speedup 1.0000x reference)
#include <cuda_runtime.h>

#define Nn 64
#define Cc 64
#define Tt 300
#define Vv 25
#define Dd 64
#define NT (Nn*Tt)        // 19200
#define VC (Vv*Cc)        // 1600
#define VD (Vv*Dd)        // 1600
#define TT1 6
#define R1 (TT1*Vv)       // 150 rows per k1 block
#define YSTR 151          // padded d-row stride in k1 staging smem
#define TV (Tt*Vv)        // 7500 floats per (n,d) plane
#define NSLOT 32
#define BN_EPS 1e-5f

typedef unsigned long long ull;

// Scratch (allocation-free: device globals)
__device__ float          g_y[(size_t)NT*VD];  // y in final (N,D,T,V) layout, pre-BN
__device__ float          g_psum[NSLOT][VD];
__device__ float          g_psq[NSLOT][VD];
__device__ float          g_sclt[Dd*Vv];       // scale indexed [d*25+v]
__device__ float          g_biat[Dd*Vv];       // bias  indexed [d*25+v]
__device__ float2         g_ms2[VC];           // [c*25+v] = (tanh(mask)+1, soff_bits)
__device__ unsigned short g_srco[Dd*Vv];       // [d*25+vout] = d_src*151 + v_src

// ---- packed f32x2 helpers (sm_100+) ----
__device__ __forceinline__ ull pack2s(float x) {
    ull r; asm("mov.b64 %0, {%1,%1};" : "=l"(r) : "f"(x)); return r;
}
__device__ __forceinline__ void fma2(ull& d, ull a, ull b) {
    asm("fma.rn.f32x2 %0, %1, %2, %0;" : "+l"(d) : "l"(a), "l"(b));
}
__device__ __forceinline__ float2 unpack2(ull v) {
    float2 f; asm("mov.b64 {%0,%1}, %2;" : "=f"(f.x), "=f"(f.y) : "l"(v)); return f;
}

// ---- prep: tables + zero stats ----
__global__ void kprep(const float* __restrict__ fm,
                      const int* __restrict__ shift_in,
                      const int* __restrict__ shift_out) {
    int idx = blockIdx.x * blockDim.x + threadIdx.x;
    if (idx < NSLOT * VD) {
        (&g_psum[0][0])[idx] = 0.0f;
        (&g_psq[0][0])[idx]  = 0.0f;
    }
    if (idx < VC) {
        int v = idx >> 6, c = idx & 63;
        int k  = shift_in[idx];
        int kv = k >> 6, kc = k & 63;
        g_ms2[c * Vv + v] = make_float2(tanhf(fm[idx]) + 1.0f,
                                        __int_as_float(kc * R1 + kv));
        int so = shift_out[idx];                 // src col for output (v, d=c)
        int vs = so >> 6, ds = so & 63;
        g_srco[c * Vv + v] = (unsigned short)(ds * YSTR + vs);
    }
}

// ---- k1: gather+mask+GEMM+bias+stats, staged transposed+shift_out write ----
__global__ void __launch_bounds__(256, 2) k1(const float* __restrict__ x0,
                                             const float* __restrict__ W,
                                             const float* __restrict__ b) {
    extern __shared__ float sm[];
    float*  xs   = sm;                              // 9600: [kc][tl*25+kv]
    float*  ys   = xs + Cc * R1;                    // 9664: [d][tl*25+v] (YSTR pad)
    float*  ws   = ys + Dd * YSTR;                  // 4096: W row-major
    float2* ms2  = (float2*)(ws + Cc * Dd);         // 1600 float2, [c*25+v]
    unsigned short* sro = (unsigned short*)(ms2 + VC);  // 1600 u16, [d*25+v]

    const int tid = threadIdx.x;
    const int nt0 = blockIdx.x * TT1;
    const int n   = nt0 / Tt;
    const int t0  = nt0 - n * Tt;                   // TT1 | Tt

    const float* xb = x0 + (size_t)n * Cc * TV + (size_t)t0 * Vv;

    // coalesced float2 slice load: xs[kc][tl*25+kv] = x0[n, kc, t0+tl, kv]
    {
        const float2* xb2 = (const float2*)xb;
        float2* xs2 = (float2*)xs;
        for (int i = tid; i < Cc * (R1 / 2); i += 256) {
            int kc   = i / (R1 / 2);
            int col2 = i - kc * (R1 / 2);
            xs2[i] = xb2[kc * (TV / 2) + col2];
        }
    }
    for (int i = tid; i < Cc * Dd; i += 256) ws[i] = W[i];
    for (int i = tid; i < VC; i += 256) { ms2[i] = g_ms2[i]; sro[i] = g_srco[i]; }
    __syncthreads();

    // 200 threads: thread (v, dt): rows (v, tl=0..5), cols d0..d0+7
    const int v  = tid >> 3;           // 0..24 (tid<200)
    const int dt = tid & 7;            // 0..7
    const int d0 = dt * 8;

    if (tid < 200) {
        ull acc[TT1][4];
        #pragma unroll
        for (int tl = 0; tl < TT1; tl++)
            #pragma unroll
            for (int k = 0; k < 4; k++) acc[tl][k] = 0ull;

        #pragma unroll 2
        for (int c = 0; c < Cc; c++) {
            float2 mo = ms2[c * Vv + v];
            const int   base = __float_as_int(mo.y);
            const float m    = mo.x;
            const ulonglong2* wp = (const ulonglong2*)(ws + c * Dd + d0);
            ulonglong2 wA = wp[0];
            ulonglong2 wB = wp[1];
            float xv[TT1];
            #pragma unroll
            for (int tl = 0; tl < TT1; tl++) xv[tl] = xs[base + tl * Vv] * m;
            #pragma unroll
            for (int tl = 0; tl < TT1; tl++) {
                ull xa = pack2s(xv[tl]);
                fma2(acc[tl][0], xa, wA.x);
                fma2(acc[tl][1], xa, wA.y);
                fma2(acc[tl][2], xa, wB.x);
                fma2(acc[tl][3], xa, wB.y);
            }
        }

        float bs[8];
        #pragma unroll
        for (int k = 0; k < 8; k++) bs[k] = b[d0 + k];

        float s[8], q[8];
        #pragma unroll
        for (int k = 0; k < 8; k++) { s[k] = 0.0f; q[k] = 0.0f; }

        // unpack per tl, write to ys immediately (no alias with xs)
        #pragma unroll
        for (int tl = 0; tl < TT1; tl++) {
            float o[8];
            #pragma unroll
            for (int k = 0; k < 4; k++) {
                float2 f = unpack2(acc[tl][k]);
                o[2*k]   = f.x + bs[2*k];
                o[2*k+1] = f.y + bs[2*k+1];
            }
            #pragma unroll
            for (int k = 0; k < 8; k++) {
                s[k] += o[k];
                q[k] += o[k] * o[k];
                ys[(d0 + k) * YSTR + tl * Vv + v] = o[k];
            }
        }

        const int slot = blockIdx.x & (NSLOT - 1);
        const int colb = v * Dd + d0;               // pre-shift (source) column
        #pragma unroll
        for (int k = 0; k < 8; k++) {
            atomicAdd(&g_psum[slot][colb + k], s[k]);
            atomicAdd(&g_psq[slot][colb + k],  q[k]);
        }
    }

    __syncthreads();

    // cooperative shift_out-gathered, transposed global write:
    // y[n][d][t0+tl][vout], 150-float contiguous runs per d
    float* yb = g_y + ((size_t)n * Dd) * TV + t0 * Vv;
    for (int i = tid; i < Dd * R1; i += 256) {
        int d = i / R1;
        int r = i - d * R1;                          // tl*25 + vout
        int tl = r / Vv;
        int vo = r - tl * Vv;
        float val = ys[tl * Vv + (int)sro[d * Vv + vo]];
        yb[(size_t)d * TV + r] = val;
    }
}

// ---- k3: reduce slots at src column, fold shift_out/gamma/beta -> tables ----
__global__ void k3(const float* __restrict__ gamma, const float* __restrict__ beta,
                   const int* __restrict__ shift_out) {
    int j = blockIdx.x * blockDim.x + threadIdx.x;
    if (j >= VD) return;
    const int src = shift_out[j];
    float s = 0.0f, q = 0.0f;
    #pragma unroll
    for (int sl = 0; sl < NSLOT; sl++) { s += g_psum[sl][src]; q += g_psq[sl][src]; }
    const float inv_n = 1.0f / (float)NT;
    float mean = s * inv_n;
    float var  = q * inv_n - mean * mean;
    float sc   = gamma[j] * rsqrtf(var + BN_EPS);
    int v = j >> 6, d = j & 63;
    g_sclt[d * Vv + v] = sc;
    g_biat[d * Vv + v] = beta[j] - mean * sc;
}

// ---- k4: pure streaming affine + residual + relu over (n,d) planes ----
__global__ void __launch_bounds__(256) k4(const float* __restrict__ x0,
                                          float* __restrict__ out) {
    __shared__ float4 s4[Vv], b4[Vv];
    const int tid = threadIdx.x;
    const int d = blockIdx.x & 63;

    if (tid < Vv) {
        int m = tid;
        const float* sp = g_sclt + d * Vv;
        const float* bp = g_biat + d * Vv;
        int v0 = (4*m) % 25, v1 = (4*m+1) % 25, v2 = (4*m+2) % 25, v3 = (4*m+3) % 25;
        s4[m] = make_float4(sp[v0], sp[v1], sp[v2], sp[v3]);
        b4[m] = make_float4(bp[v0], bp[v1], bp[v2], bp[v3]);
    }
    __syncthreads();

    const size_t base = (size_t)blockIdx.x * TV;     // (n*64+d)*7500
    const float4* yp = (const float4*)(g_y + base);
    const float4* xp = (const float4*)(x0 + base);
    float4* op = (float4*)(out + base);

    #pragma unroll 2
    for (int i = tid; i < TV / 4; i += 256) {        // 1875 float4
        int m = i % 25;
        float4 y = yp[i];
        float4 x = xp[i];
        float4 s = s4[m];
        float4 bb = b4[m];
        float4 r;
        r.x = fmaxf(fmaf(y.x, s.x, bb.x) + x.x, 0.0f);
        r.y = fmaxf(fmaf(y.y, s.y, bb.y) + x.y, 0.0f);
        r.z = fmaxf(fmaf(y.z, s.z, bb.z) + x.z, 0.0f);
        r.w = fmaxf(fmaf(y.w, s.w, bb.w) + x.w, 0.0f);
        op[i] = r;
    }
}

extern "C" void kernel_launch(void* const* d_in, const int* in_sizes, int n_in,
                              void* d_out, int out_size) {
    const float* x0        = (const float*)d_in[0];
    const float* fm        = (const float*)d_in[1];
    const float* W         = (const float*)d_in[2];
    const float* b         = (const float*)d_in[3];
    const float* gamma     = (const float*)d_in[4];
    const float* beta      = (const float*)d_in[5];
    const int*   shift_in  = (const int*)d_in[6];
    const int*   shift_out = (const int*)d_in[7];
    float* out = (float*)d_out;

    // xs 38400 + ys 38656 + ws 16384 + ms2 12800 + sro 3200 = 109440 B
    const int smem1 = (Cc * R1 + Dd * YSTR + Cc * Dd) * 4 + VC * 8 + VC * 2;
    cudaFuncSetAttribute(k1, cudaFuncAttributeMaxDynamicSharedMemorySize, smem1);

    kprep<<<(NSLOT * VD + 255) / 256, 256>>>(fm, shift_in, shift_out);
    k1<<<NT / TT1, 256, smem1>>>(x0, W, b);
    k3<<<(VD + 255) / 256, 256>>>(gamma, beta, shift_out);
    k4<<<Nn * Dd, 256>>>(x0, out);
}

// round 6
// speedup vs baseline: 1.1652x; 1.1652x over previous
#include <cuda_runtime.h>

#define Nn 64
#define Cc 64
#define Tt 300
#define Vv 25
#define Dd 64
#define NT (Nn*Tt)        // 19200
#define VC (Vv*Cc)        // 1600
#define VD (Vv*Dd)        // 1600
#define TT1 6
#define R1 (TT1*Vv)       // 150 rows per k1 block
#define YSTR 151          // padded d-row stride in k1 staging smem
#define TV (Tt*Vv)        // 7500 floats per (n,d) plane
#define NSLOT 32
#define BN_EPS 1e-5f

// smem float offsets for k1 (total 17696 floats = 70784 B)
#define OFF_SRO 0                 // 1600 u16 = 800 floats
#define OFF_XS  800               // 9600 floats
#define OFF_WS  (800+9600)        // 4096 floats
#define OFF_MS2 (800+9600+4096)   // 3200 floats (1600 float2)
#define SM_TOT  17696
#define OFF_YS  (SM_TOT - Dd*YSTR)   // 8032: overlays xs tail + ws + ms2 (all dead)

typedef unsigned long long ull;

// Scratch (allocation-free: device globals)
__device__ float          g_y[(size_t)NT*VD];  // y in final (N,D,T,V) layout, pre-BN
__device__ float          g_psum[NSLOT][VD];
__device__ float          g_psq[NSLOT][VD];
__device__ float          g_sclt[Dd*Vv];       // scale indexed [d*25+v]
__device__ float          g_biat[Dd*Vv];       // bias  indexed [d*25+v]
__device__ float2         g_ms2[VC];           // [c*25+v] = (tanh(mask)+1, soff_bits)
__device__ unsigned short g_srco[Dd*Vv];       // [d*25+vout] = tl-local src = v_src? no: d_src*? see kprep

// ---- packed f32x2 helpers (sm_100+) ----
__device__ __forceinline__ ull pack2s(float x) {
    ull r; asm("mov.b64 %0, {%1,%1};" : "=l"(r) : "f"(x)); return r;
}
__device__ __forceinline__ void fma2(ull& d, ull a, ull b) {
    asm("fma.rn.f32x2 %0, %1, %2, %0;" : "+l"(d) : "l"(a), "l"(b));
}
__device__ __forceinline__ void add2(ull& d, ull a) {
    asm("add.rn.f32x2 %0, %0, %1;" : "+l"(d) : "l"(a));
}
__device__ __forceinline__ void fma2q(ull& q, ull o) {
    asm("fma.rn.f32x2 %0, %1, %1, %0;" : "+l"(q) : "l"(o));
}
__device__ __forceinline__ float2 unpack2(ull v) {
    float2 f; asm("mov.b64 {%0,%1}, %2;" : "=f"(f.x), "=f"(f.y) : "l"(v)); return f;
}

// ---- prep: tables + zero stats ----
__global__ void kprep(const float* __restrict__ fm,
                      const int* __restrict__ shift_in,
                      const int* __restrict__ shift_out) {
    int idx = blockIdx.x * blockDim.x + threadIdx.x;
    if (idx < NSLOT * VD) {
        (&g_psum[0][0])[idx] = 0.0f;
        (&g_psq[0][0])[idx]  = 0.0f;
    }
    if (idx < VC) {
        int v = idx >> 6, c = idx & 63;
        int k  = shift_in[idx];
        int kv = k >> 6, kc = k & 63;
        g_ms2[c * Vv + v] = make_float2(tanhf(fm[idx]) + 1.0f,
                                        __int_as_float(kc * R1 + kv));
        int so = shift_out[idx];                 // src col for output (v, d=c)
        int vs = so >> 6, ds = so & 63;
        g_srco[c * Vv + v] = (unsigned short)(ds * YSTR + vs);
    }
}

// ---- k1: gather+mask+GEMM+bias+stats, staged transposed+shift_out write ----
__global__ void __launch_bounds__(256, 3) k1(const float* __restrict__ x0,
                                             const float* __restrict__ W,
                                             const float* __restrict__ b) {
    extern __shared__ float sm[];
    unsigned short* sro = (unsigned short*)(sm + OFF_SRO);  // [d*25+vout]
    float*  xs   = sm + OFF_XS;                  // [kc][tl*25+kv]
    float*  ws   = sm + OFF_WS;                  // W row-major
    float2* ms2  = (float2*)(sm + OFF_MS2);      // [c*25+v]
    float*  ys   = sm + OFF_YS;                  // [d][tl*25+v], overlays dead regions

    const int tid = threadIdx.x;
    const int nt0 = blockIdx.x * TT1;
    const int n   = nt0 / Tt;
    const int t0  = nt0 - n * Tt;                // TT1 | Tt

    const float* xb = x0 + (size_t)n * Cc * TV + (size_t)t0 * Vv;

    // coalesced float2 slice load: xs[kc][tl*25+kv] = x0[n, kc, t0+tl, kv]
    {
        const float2* xb2 = (const float2*)xb;
        float2* xs2 = (float2*)xs;
        for (int i = tid; i < Cc * (R1 / 2); i += 256) {
            int kc   = i / (R1 / 2);
            int col2 = i - kc * (R1 / 2);
            xs2[i] = xb2[kc * (TV / 2) + col2];
        }
    }
    for (int i = tid; i < Cc * Dd; i += 256) ws[i] = W[i];
    for (int i = tid; i < VC; i += 256) { ms2[i] = g_ms2[i]; sro[i] = g_srco[i]; }
    __syncthreads();

    // 200 threads: thread (v, dt): rows (v, tl=0..5), cols d0..d0+7
    const int v  = tid >> 3;           // 0..24 (tid<200)
    const int dt = tid & 7;            // 0..7
    const int d0 = dt * 8;

    ull acc[TT1][4];
    if (tid < 200) {
        #pragma unroll
        for (int tl = 0; tl < TT1; tl++)
            #pragma unroll
            for (int k = 0; k < 4; k++) acc[tl][k] = 0ull;

        #pragma unroll 2
        for (int c = 0; c < Cc; c++) {
            float2 mo = ms2[c * Vv + v];
            const int   base = __float_as_int(mo.y);
            const float m    = mo.x;
            const ulonglong2* wp = (const ulonglong2*)(ws + c * Dd + d0);
            ulonglong2 wA = wp[0];
            ulonglong2 wB = wp[1];
            float xv[TT1];
            #pragma unroll
            for (int tl = 0; tl < TT1; tl++) xv[tl] = xs[base + tl * Vv] * m;
            #pragma unroll
            for (int tl = 0; tl < TT1; tl++) {
                ull xa = pack2s(xv[tl]);
                fma2(acc[tl][0], xa, wA.x);
                fma2(acc[tl][1], xa, wA.y);
                fma2(acc[tl][2], xa, wB.x);
                fma2(acc[tl][3], xa, wB.y);
            }
        }

        // packed bias add (b is 256B-aligned harness alloc; d0 multiple of 8)
        const ull* bp = (const ull*)(b + d0);
        ull b0 = bp[0], b1 = bp[1], b2 = bp[2], b3 = bp[3];
        #pragma unroll
        for (int tl = 0; tl < TT1; tl++) {
            add2(acc[tl][0], b0);
            add2(acc[tl][1], b1);
            add2(acc[tl][2], b2);
            add2(acc[tl][3], b3);
        }
    }

    __syncthreads();   // xs/ws/ms2 now dead; ys overlays them

    if (tid < 200) {
        ull s2[4], q2[4];
        #pragma unroll
        for (int k = 0; k < 4; k++) { s2[k] = 0ull; q2[k] = 0ull; }

        #pragma unroll
        for (int tl = 0; tl < TT1; tl++) {
            const int rbase = tl * Vv + v;
            #pragma unroll
            for (int k = 0; k < 4; k++) {
                ull o2 = acc[tl][k];
                add2(s2[k], o2);
                fma2q(q2[k], o2);
                float2 f = unpack2(o2);
                ys[(d0 + 2*k    ) * YSTR + rbase] = f.x;
                ys[(d0 + 2*k + 1) * YSTR + rbase] = f.y;
            }
        }

        const int slot = blockIdx.x & (NSLOT - 1);
        const int colb = v * Dd + d0;            // pre-shift (source) column
        #pragma unroll
        for (int k = 0; k < 4; k++) {
            float2 fs = unpack2(s2[k]);
            float2 fq = unpack2(q2[k]);
            atomicAdd(&g_psum[slot][colb + 2*k    ], fs.x);
            atomicAdd(&g_psum[slot][colb + 2*k + 1], fs.y);
            atomicAdd(&g_psq[slot][colb + 2*k    ], fq.x);
            atomicAdd(&g_psq[slot][colb + 2*k + 1], fq.y);
        }
    }

    __syncthreads();

    // cooperative shift_out-gathered, transposed global write:
    // y[n][d][t0+tl][vout], 150-float contiguous runs per d
    float* yb = g_y + ((size_t)n * Dd) * TV + t0 * Vv;
    for (int i = tid; i < Dd * R1; i += 256) {
        int d = i / R1;
        int r = i - d * R1;                      // tl*25 + vout
        int tl = r / Vv;
        int vo = r - tl * Vv;
        float val = ys[tl * Vv + (int)sro[d * Vv + vo]];
        yb[(size_t)d * TV + r] = val;
    }
}

// ---- k3: reduce slots at src column, fold shift_out/gamma/beta -> tables ----
__global__ void k3(const float* __restrict__ gamma, const float* __restrict__ beta,
                   const int* __restrict__ shift_out) {
    int j = blockIdx.x * blockDim.x + threadIdx.x;
    if (j >= VD) return;
    const int src = shift_out[j];
    float s = 0.0f, q = 0.0f;
    #pragma unroll
    for (int sl = 0; sl < NSLOT; sl++) { s += g_psum[sl][src]; q += g_psq[sl][src]; }
    const float inv_n = 1.0f / (float)NT;
    float mean = s * inv_n;
    float var  = q * inv_n - mean * mean;
    float sc   = gamma[j] * rsqrtf(var + BN_EPS);
    int v = j >> 6, d = j & 63;
    g_sclt[d * Vv + v] = sc;
    g_biat[d * Vv + v] = beta[j] - mean * sc;
}

// ---- k4: pure streaming affine + residual + relu over (n,d) planes ----
__global__ void __launch_bounds__(256) k4(const float* __restrict__ x0,
                                          float* __restrict__ out) {
    __shared__ float4 s4[Vv], b4[Vv];
    const int tid = threadIdx.x;
    const int d = blockIdx.x & 63;

    if (tid < Vv) {
        int m = tid;
        const float* sp = g_sclt + d * Vv;
        const float* bp = g_biat + d * Vv;
        int v0 = (4*m) % 25, v1 = (4*m+1) % 25, v2 = (4*m+2) % 25, v3 = (4*m+3) % 25;
        s4[m] = make_float4(sp[v0], sp[v1], sp[v2], sp[v3]);
        b4[m] = make_float4(bp[v0], bp[v1], bp[v2], bp[v3]);
    }
    __syncthreads();

    const size_t base = (size_t)blockIdx.x * TV;     // (n*64+d)*7500
    const float4* yp = (const float4*)(g_y + base);
    const float4* xp = (const float4*)(x0 + base);
    float4* op = (float4*)(out + base);

    #pragma unroll 2
    for (int i = tid; i < TV / 4; i += 256) {        // 1875 float4
        int m = i % 25;
        float4 y = yp[i];
        float4 x = xp[i];
        float4 s = s4[m];
        float4 bb = b4[m];
        float4 r;
        r.x = fmaxf(fmaf(y.x, s.x, bb.x) + x.x, 0.0f);
        r.y = fmaxf(fmaf(y.y, s.y, bb.y) + x.y, 0.0f);
        r.z = fmaxf(fmaf(y.z, s.z, bb.z) + x.z, 0.0f);
        r.w = fmaxf(fmaf(y.w, s.w, bb.w) + x.w, 0.0f);
        op[i] = r;
    }
}

extern "C" void kernel_launch(void* const* d_in, const int* in_sizes, int n_in,
                              void* d_out, int out_size) {
    const float* x0        = (const float*)d_in[0];
    const float* fm        = (const float*)d_in[1];
    const float* W         = (const float*)d_in[2];
    const float* b         = (const float*)d_in[3];
    const float* gamma     = (const float*)d_in[4];
    const float* beta      = (const float*)d_in[5];
    const int*   shift_in  = (const int*)d_in[6];
    const int*   shift_out = (const int*)d_in[7];
    float* out = (float*)d_out;

    const int smem1 = SM_TOT * 4;                    // 70784 B -> 3 CTAs/SM
    cudaFuncSetAttribute(k1, cudaFuncAttributeMaxDynamicSharedMemorySize, smem1);

    kprep<<<(NSLOT * VD + 255) / 256, 256>>>(fm, shift_in, shift_out);
    k1<<<NT / TT1, 256, smem1>>>(x0, W, b);
    k3<<<(VD + 255) / 256, 256>>>(gamma, beta, shift_out);
    k4<<<Nn * Dd, 256>>>(x0, out);
}